// round 11
// baseline (speedup 1.0000x reference)
#include <cuda_runtime.h>
#include <cuda_bf16.h>

#define N_NODES 20000
#define N_EDGES 5000
#define STEPS 50
#define NODE_STRIDE 64      // max edges per node (mean ~10, Poisson tail safe)
#define NE_REG 24           // node->edge indices kept in registers (P(>24)~5e-5)

#define NBLK 148            // <= SM count -> co-resident at occ 1
#define NTHR 1024           // 32 warps/CTA: restores outstanding-load capacity
#define NODES_PER_CTA 136   // 148*136 = 20128 >= 20000

// ---------------- scratch (device globals: no allocation allowed) ----------
__device__ int   g_node_cnt[N_NODES];
__device__ int   g_node_edges[N_NODES * NODE_STRIDE];
__device__ float g_aggs[STEPS * N_EDGES];   // per-step edge accumulators (1MB)

// flag barrier state (monotonic -> graph-replay safe; 32B-padded slots)
__device__ unsigned g_flags[NBLK * 8];
__device__ unsigned g_gen;

// ---------------- acquire/release helpers (gpu scope, no SYS volatile) ------
__device__ __forceinline__ unsigned ld_acq(const unsigned* p) {
    unsigned v;
    asm volatile("ld.global.acquire.gpu.u32 %0, [%1];" : "=r"(v) : "l"(p) : "memory");
    return v;
}
__device__ __forceinline__ void st_rel(unsigned* p, unsigned v) {
    asm volatile("st.global.release.gpu.u32 [%0], %1;" :: "l"(p), "r"(v) : "memory");
}

// ---------------- init: zero node counts + accumulators, traj[0] = x --------
__global__ void k_init(const float* __restrict__ x, float* __restrict__ out) {
    int i = blockIdx.x * blockDim.x + threadIdx.x;
    if (i < STEPS * N_EDGES) g_aggs[i] = 0.f;
    if (i < N_NODES) {
        g_node_cnt[i] = 0;
        out[i * 3 + 0] = x[i * 3 + 0];
        out[i * 3 + 1] = x[i * 3 + 1];
        out[i * 3 + 2] = x[i * 3 + 2];
    }
}

// ---------------- build node->edge lists (one atomic per nonzero) -----------
// H row-major [N_EDGES][N_NODES]; N_NODES % 4 == 0 so float4 stays in-row.
__global__ void k_build(const float4* __restrict__ H4) {
    const int row4   = N_NODES / 4;            // 5000 float4 per edge row
    const int total4 = N_EDGES * row4;         // 25M
    int stride = gridDim.x * blockDim.x;
    for (int i = blockIdx.x * blockDim.x + threadIdx.x; i < total4; i += stride) {
        float4 v = H4[i];
        if (v.x != 0.f || v.y != 0.f || v.z != 0.f || v.w != 0.f) {
            int e  = i / row4;
            int nb = (i - e * row4) * 4;
            float vals[4] = {v.x, v.y, v.z, v.w};
            #pragma unroll
            for (int k = 0; k < 4; k++) {
                if (vals[k] != 0.f) {
                    int nn = nb + k;
                    int q = atomicAdd(&g_node_cnt[nn], 1);
                    if (q < NODE_STRIDE) g_node_edges[nn * NODE_STRIDE + q] = e;
                }
            }
        }
    }
}

// ---------------- flag barrier: parallel arrive/detect, acq/rel ordering ----
__device__ __forceinline__ void gsync(unsigned barno) {
    __syncthreads();
    if (blockIdx.x == 0) {
        if (threadIdx.x == 0) st_rel(&g_flags[0], barno);
        if (threadIdx.x < NBLK) {                          // parallel detect
            while (ld_acq(&g_flags[threadIdx.x * 8]) < barno) { }
        }
        __syncthreads();                                   // all flags seen
        if (threadIdx.x == 0) st_rel(&g_gen, barno);       // publish
    } else {
        if (threadIdx.x == 0) {
            st_rel(&g_flags[blockIdx.x * 8], barno);       // orders prior REDs
            while (ld_acq(&g_gen) < barno) { }
        }
    }
    __syncthreads();
}

// ---------------- persistent: 49 steps, ONE barrier per step ----------------
// Owner threads are spread across all 32 warps (lanes 0..4 of each warp) so
// the per-CTA gather (~1350 loads) and scatter (~1350 REDs) fit in the
// outstanding-load window of 32 warps -> ~1 L2 round trip per phase.
__global__ void __launch_bounds__(NTHR, 1)
sir_steps(const float* __restrict__ x,
          const float* __restrict__ beta,
          const float* __restrict__ gamma,
          float*       __restrict__ out) {
    const int tid = threadIdx.x;
    // inverse owner map: k = lane*32 + warp  (active lanes 0..4 in each warp)
    const int k = (tid & 31) * 32 + (tid >> 5);
    const int n = (k < NODES_PER_CTA) ? (blockIdx.x * NODES_PER_CTA + k) : N_NODES;
    const bool act = (n < N_NODES);

    // barrier base: monotonic across graph replays
    __shared__ unsigned s_base;
    if (tid == 0) s_base = ld_acq(&g_gen);
    __syncthreads();
    unsigned barno = s_base + 1;

    // hoist node state + adjacency into registers (from previous launches:
    // coherent plain loads, immutable here)
    float S = 0.f, I = 0.f, R = 0.f, bn = 0.f, gn = 0.f;
    int   ncnt = 0;
    int   ereg[NE_REG];
    if (act) {
        S  = x[n * 3 + 0];
        I  = x[n * 3 + 1];
        R  = x[n * 3 + 2];
        bn = beta[n];
        gn = gamma[n];
        ncnt = g_node_cnt[n];
        ncnt = (ncnt < NODE_STRIDE) ? ncnt : NODE_STRIDE;
    }
    #pragma unroll
    for (int j = 0; j < NE_REG; j++)
        ereg[j] = (act && j < ncnt) ? g_node_edges[n * NODE_STRIDE + j] : -1;

    // initial scatter: I_0 into step-0 accumulators
    if (act) {
        #pragma unroll
        for (int j = 0; j < NE_REG; j++)
            if (ereg[j] >= 0) atomicAdd(&g_aggs[ereg[j]], I);
        for (int j = NE_REG; j < ncnt; j++)          // rare tail
            atomicAdd(&g_aggs[g_node_edges[n * NODE_STRIDE + j]], I);
    }
    gsync(barno); barno++;

    for (int t = 1; t < STEPS; t++) {
        const float* buf = g_aggs + (t - 1) * N_EDGES;   // complete after barrier
        if (act) {
            // gather: back = H^T (H I_{t-1}) restricted to this node
            float back = 0.f;
            #pragma unroll
            for (int j = 0; j < NE_REG; j++)
                if (ereg[j] >= 0) back += __ldcg(&buf[ereg[j]]);
            for (int j = NE_REG; j < ncnt; j++)
                back += __ldcg(&buf[g_node_edges[n * NODE_STRIDE + j]]);

            float nc = bn * S * back;     // new cases
            float nr = gn * I;            // new recoveries

            float s0 = fmaxf(S - nc,      0.f);
            float s1 = fmaxf(I + nc - nr, 0.f);
            float s2 = fmaxf(R + nr,      0.f);
            float inv = 1.f / (s0 + s1 + s2);
            S = s0 * inv; I = s1 * inv; R = s2 * inv;

            float* cur = out + (long)t * (N_NODES * 3) + n * 3;
            cur[0] = S; cur[1] = I; cur[2] = R;

            // scatter new I into step-t accumulators (feeds step t+1)
            if (t < STEPS - 1) {
                float* nxt = g_aggs + t * N_EDGES;
                #pragma unroll
                for (int j = 0; j < NE_REG; j++)
                    if (ereg[j] >= 0) atomicAdd(&nxt[ereg[j]], I);
                for (int j = NE_REG; j < ncnt; j++)
                    atomicAdd(&nxt[g_node_edges[n * NODE_STRIDE + j]], I);
            }
        }
        if (t < STEPS - 1) { gsync(barno); barno++; }
    }
}

// ---------------- launcher --------------------------------------------------
extern "C" void kernel_launch(void* const* d_in, const int* in_sizes, int n_in,
                              void* d_out, int out_size) {
    const float*  x     = (const float*) d_in[0];
    const float4* H4    = (const float4*)d_in[1];
    const float*  beta  = (const float*) d_in[2];
    const float*  gamma = (const float*) d_in[3];
    float*        out   = (float*)d_out;

    k_init  <<<(STEPS * N_EDGES + 255) / 256, 256>>>(x, out);
    k_build <<<4096, 256>>>(H4);
    sir_steps<<<NBLK, NTHR>>>(x, beta, gamma, out);
}

// round 12
// speedup vs baseline: 1.4212x; 1.4212x over previous
#include <cuda_runtime.h>
#include <cuda_bf16.h>

#define N_NODES 20000
#define N_EDGES 5000
#define STEPS 50
#define EDGE_STRIDE 128     // max nodes per edge (mean ~40, Poisson tail safe)
#define POS_PER_LANE 4      // EDGE_STRIDE / 32

// ---------------- scratch (device globals: no allocation allowed) ----------
__device__ int   g_edge_cnt[N_EDGES];
__device__ int   g_edge_nodes[N_EDGES * EDGE_STRIDE];
__device__ float g_back[STEPS * N_NODES];   // per-step node accumulators (4MB)
__device__ float g_S[N_NODES];              // SoA state (coalesced 4B access)
__device__ float g_I[N_NODES];
__device__ float g_R[N_NODES];

// ---------------- init: zero counters + accumulators, traj[0] = x, seed SoA -
__global__ void k_init(const float* __restrict__ x, float* __restrict__ out) {
    int i = blockIdx.x * blockDim.x + threadIdx.x;
    if (i < STEPS * N_NODES) g_back[i] = 0.f;
    if (i < N_EDGES) g_edge_cnt[i] = 0;
    if (i < N_NODES) {
        float s  = x[i * 3 + 0];
        float in = x[i * 3 + 1];
        float r  = x[i * 3 + 2];
        out[i * 3 + 0] = s;
        out[i * 3 + 1] = in;
        out[i * 3 + 2] = r;
        g_S[i] = s; g_I[i] = in; g_R[i] = r;
    }
}

// ---------------- build edge->node lists (ONE atomic per nonzero) -----------
// H row-major [N_EDGES][N_NODES]; N_NODES % 4 == 0 so float4 stays in-row.
__global__ void k_build(const float4* __restrict__ H4) {
    const int row4   = N_NODES / 4;            // 5000 float4 per edge row
    const int total4 = N_EDGES * row4;         // 25M
    int stride = gridDim.x * blockDim.x;
    for (int i = blockIdx.x * blockDim.x + threadIdx.x; i < total4; i += stride) {
        float4 v = H4[i];
        if (v.x != 0.f || v.y != 0.f || v.z != 0.f || v.w != 0.f) {
            int e  = i / row4;
            int nb = (i - e * row4) * 4;
            float vals[4] = {v.x, v.y, v.z, v.w};
            #pragma unroll
            for (int k = 0; k < 4; k++) {
                if (vals[k] != 0.f) {
                    int p = atomicAdd(&g_edge_cnt[e], 1);
                    if (p < EDGE_STRIDE) g_edge_nodes[e * EDGE_STRIDE + p] = nb + k;
                }
            }
        }
    }
}

// ---------------- per step, kernel 1: gather + reduce + SCATTER -------------
// warp per edge: s = sum_{n in e} I[n]; then RED.F32 s into g_back[t][n] for
// every member node. All lanes hold s after the butterfly -> scatter is
// fully parallel and fire-and-forget (no read-back).
__global__ void k_agg(int t) {
    int e    = (blockIdx.x * blockDim.x + threadIdx.x) >> 5;
    int lane = threadIdx.x & 31;
    if (e >= N_EDGES) return;

    int cnt = g_edge_cnt[e];
    cnt = (cnt < EDGE_STRIDE) ? cnt : EDGE_STRIDE;

    // batch idx loads (independent), then batch gathers (independent)
    int idx[POS_PER_LANE];
    #pragma unroll
    for (int k = 0; k < POS_PER_LANE; k++) {
        int j = lane + 32 * k;
        idx[k] = (j < cnt) ? g_edge_nodes[e * EDGE_STRIDE + j] : -1;
    }
    float s = 0.f;
    #pragma unroll
    for (int k = 0; k < POS_PER_LANE; k++)
        if (idx[k] >= 0) s += g_I[idx[k]];

    #pragma unroll
    for (int o = 16; o; o >>= 1) s += __shfl_xor_sync(0xffffffffu, s, o);

    float* back = g_back + t * N_NODES;
    #pragma unroll
    for (int k = 0; k < POS_PER_LANE; k++)
        if (idx[k] >= 0) atomicAdd(&back[idx[k]], s);
}

// ---------------- per step, kernel 2: chain-free SIR update ------------------
// 6 coalesced loads, compute, 4 stores. No indirection at all.
__global__ void k_update(const float* __restrict__ beta,
                         const float* __restrict__ gamma,
                         float* __restrict__ out, int t) {
    int n = blockIdx.x * blockDim.x + threadIdx.x;
    if (n >= N_NODES) return;

    float back = g_back[t * N_NODES + n];
    float S = g_S[n], I = g_I[n], R = g_R[n];

    float nc = beta[n]  * S * back;   // new cases
    float nr = gamma[n] * I;          // new recoveries

    float s0 = fmaxf(S - nc,      0.f);
    float s1 = fmaxf(I + nc - nr, 0.f);
    float s2 = fmaxf(R + nr,      0.f);
    float inv = 1.f / (s0 + s1 + s2);
    s0 *= inv; s1 *= inv; s2 *= inv;

    g_S[n] = s0; g_I[n] = s1; g_R[n] = s2;

    float* cur = out + (long)t * (N_NODES * 3) + n * 3;
    cur[0] = s0; cur[1] = s1; cur[2] = s2;
}

// ---------------- launcher --------------------------------------------------
extern "C" void kernel_launch(void* const* d_in, const int* in_sizes, int n_in,
                              void* d_out, int out_size) {
    const float*  x     = (const float*) d_in[0];
    const float4* H4    = (const float4*)d_in[1];
    const float*  beta  = (const float*) d_in[2];
    const float*  gamma = (const float*) d_in[3];
    float*        out   = (float*)d_out;

    k_init <<<(STEPS * N_NODES + 255) / 256, 256>>>(x, out);
    k_build<<<4096, 256>>>(H4);

    for (int t = 1; t < STEPS; t++) {
        k_agg   <<<(N_EDGES * 32 + 255) / 256, 256>>>(t);
        k_update<<<(N_NODES + 255) / 256, 256>>>(beta, gamma, out, t);
    }
}

// round 13
// speedup vs baseline: 1.4594x; 1.0269x over previous
#include <cuda_runtime.h>
#include <cuda_bf16.h>

#define N_NODES 20000
#define N_EDGES 5000
#define STEPS 50
#define EDGE_STRIDE 128     // max nodes per edge (mean ~40, Poisson tail safe)
#define POS_PER_LANE 4      // EDGE_STRIDE / 32

#define NODE_CTAS 79        // 79*256 = 20224 >= 20000
#define EDGE_CTAS 625       // 625*8 warps = 5000 edges (warp per edge)

// ---------------- scratch (device globals: no allocation allowed) ----------
__device__ int    g_edge_cnt[N_EDGES];
__device__ int    g_edge_nodes[N_EDGES * EDGE_STRIDE];
__device__ float  g_back[STEPS * N_NODES];    // per-step node accumulators (4MB)
__device__ float4 g_state[2][N_NODES];        // ping-pong (S,I,R,_) 16B aligned
__device__ float2 g_bg[N_NODES];              // packed (beta, gamma)

// ---------------- shared SIR step math (FP-identical in both parts) ---------
__device__ __forceinline__ float3 sir_next(float S, float I, float R,
                                           float back, float b, float g) {
    float nc = b * S * back;          // new cases
    float nr = g * I;                 // new recoveries
    float s0 = fmaxf(S - nc,      0.f);
    float s1 = fmaxf(I + nc - nr, 0.f);
    float s2 = fmaxf(R + nr,      0.f);
    float inv = 1.f / (s0 + s1 + s2);
    return make_float3(s0 * inv, s1 * inv, s2 * inv);
}

// ---------------- init: zero scratch, traj[0] = x, pack state/bg ------------
__global__ void k_init(const float* __restrict__ x,
                       const float* __restrict__ beta,
                       const float* __restrict__ gamma,
                       float* __restrict__ out) {
    int i = blockIdx.x * blockDim.x + threadIdx.x;
    if (i < STEPS * N_NODES) g_back[i] = 0.f;
    if (i < N_EDGES) g_edge_cnt[i] = 0;
    if (i < N_NODES) {
        float s  = x[i * 3 + 0];
        float in = x[i * 3 + 1];
        float r  = x[i * 3 + 2];
        out[i * 3 + 0] = s;
        out[i * 3 + 1] = in;
        out[i * 3 + 2] = r;
        g_state[0][i] = make_float4(s, in, r, 0.f);
        g_bg[i] = make_float2(beta[i], gamma[i]);
    }
}

// ---------------- build edge->node lists (one atomic per nonzero) -----------
// H row-major [N_EDGES][N_NODES]; N_NODES % 4 == 0 so float4 stays in-row.
__global__ void k_build(const float4* __restrict__ H4) {
    const int row4   = N_NODES / 4;            // 5000 float4 per edge row
    const int total4 = N_EDGES * row4;         // 25M
    int stride = gridDim.x * blockDim.x;
    for (int i = blockIdx.x * blockDim.x + threadIdx.x; i < total4; i += stride) {
        float4 v = H4[i];
        if (v.x != 0.f || v.y != 0.f || v.z != 0.f || v.w != 0.f) {
            int e  = i / row4;
            int nb = (i - e * row4) * 4;
            float vals[4] = {v.x, v.y, v.z, v.w};
            #pragma unroll
            for (int k = 0; k < 4; k++) {
                if (vals[k] != 0.f) {
                    int p = atomicAdd(&g_edge_cnt[e], 1);
                    if (p < EDGE_STRIDE) g_edge_nodes[e * EDGE_STRIDE + p] = nb + k;
                }
            }
        }
    }
}

// ---------------- agg0: back[0] = H^T (H I_0)  (warp per edge) --------------
__global__ void k_agg0() {
    int e    = (blockIdx.x * blockDim.x + threadIdx.x) >> 5;
    int lane = threadIdx.x & 31;
    if (e >= N_EDGES) return;
    int cnt = g_edge_cnt[e];
    cnt = (cnt < EDGE_STRIDE) ? cnt : EDGE_STRIDE;

    int idx[POS_PER_LANE];
    #pragma unroll
    for (int k = 0; k < POS_PER_LANE; k++) {
        int j = lane + 32 * k;
        idx[k] = (j < cnt) ? g_edge_nodes[e * EDGE_STRIDE + j] : -1;
    }
    float s = 0.f;
    #pragma unroll
    for (int k = 0; k < POS_PER_LANE; k++)
        if (idx[k] >= 0) s += g_state[0][idx[k]].y;
    #pragma unroll
    for (int o = 16; o; o >>= 1) s += __shfl_xor_sync(0xffffffffu, s, o);
    #pragma unroll
    for (int k = 0; k < POS_PER_LANE; k++)
        if (idx[k] >= 0) atomicAdd(&g_back[idx[k]], s);
}

// ---------------- fused per-step kernel -------------------------------------
// CTAs [0, NODE_CTAS):    node update from (state[t-1], back[t-1]) -> state[t], out[t]
// CTAs [NODE_CTAS, ...):  edge warps RECOMPUTE member I_t from the same step-t-1
//                         data (FP-identical), reduce, scatter into back[t].
// Both parts depend only on prior-launch data -> no intra-kernel ordering.
__global__ void k_step(float* __restrict__ out, int t) {
    const float4* st_prev = g_state[(t - 1) & 1];
    const float*  back_in = g_back + (t - 1) * N_NODES;

    if (blockIdx.x < NODE_CTAS) {
        int n = blockIdx.x * blockDim.x + threadIdx.x;
        if (n >= N_NODES) return;
        float4 st = st_prev[n];
        float2 bg = g_bg[n];
        float3 nx = sir_next(st.x, st.y, st.z, back_in[n], bg.x, bg.y);

        g_state[t & 1][n] = make_float4(nx.x, nx.y, nx.z, 0.f);
        float* cur = out + (long)t * (N_NODES * 3) + n * 3;
        cur[0] = nx.x; cur[1] = nx.y; cur[2] = nx.z;
    } else {
        if (t >= STEPS - 1) return;            // back[STEPS-1] never consumed
        int e    = ((blockIdx.x - NODE_CTAS) * blockDim.x + threadIdx.x) >> 5;
        int lane = threadIdx.x & 31;
        if (e >= N_EDGES) return;
        int cnt = g_edge_cnt[e];
        cnt = (cnt < EDGE_STRIDE) ? cnt : EDGE_STRIDE;

        int idx[POS_PER_LANE];
        #pragma unroll
        for (int k = 0; k < POS_PER_LANE; k++) {
            int j = lane + 32 * k;
            idx[k] = (j < cnt) ? g_edge_nodes[e * EDGE_STRIDE + j] : -1;
        }
        // recompute I_t for member nodes (identical math to node part)
        float s = 0.f;
        #pragma unroll
        for (int k = 0; k < POS_PER_LANE; k++) {
            if (idx[k] >= 0) {
                int n = idx[k];
                float4 st = st_prev[n];
                float2 bg = g_bg[n];
                float3 nx = sir_next(st.x, st.y, st.z, back_in[n], bg.x, bg.y);
                s += nx.y;
            }
        }
        #pragma unroll
        for (int o = 16; o; o >>= 1) s += __shfl_xor_sync(0xffffffffu, s, o);

        float* back_out = g_back + t * N_NODES;
        #pragma unroll
        for (int k = 0; k < POS_PER_LANE; k++)
            if (idx[k] >= 0) atomicAdd(&back_out[idx[k]], s);
    }
}

// ---------------- launcher --------------------------------------------------
extern "C" void kernel_launch(void* const* d_in, const int* in_sizes, int n_in,
                              void* d_out, int out_size) {
    const float*  x     = (const float*) d_in[0];
    const float4* H4    = (const float4*)d_in[1];
    const float*  beta  = (const float*) d_in[2];
    const float*  gamma = (const float*) d_in[3];
    float*        out   = (float*)d_out;

    k_init <<<(STEPS * N_NODES + 255) / 256, 256>>>(x, beta, gamma, out);
    k_build<<<4096, 256>>>(H4);
    k_agg0 <<<(N_EDGES * 32 + 255) / 256, 256>>>();

    for (int t = 1; t < STEPS - 1; t++)
        k_step<<<NODE_CTAS + EDGE_CTAS, 256>>>(out, t);
    k_step<<<NODE_CTAS, 256>>>(out, STEPS - 1);   // last: node part only
}